// round 13
// baseline (speedup 1.0000x reference)
#include <cuda_runtime.h>
#include <cstddef>

typedef unsigned long long ULL;
typedef ulonglong2 UL2;

#define EPSF 1e-5f
#define NB 8
#define HW 256
#define NODES 340      // 4 views * 5 T * 17 V
#define PL 680         // plane stride in floats (340 nodes x float2)

// ---- parameter table layout (floats) ----
#define CASP 0         // A_sp padded: 4*17 rows x 20  = 1360
#define CATM 1360      // A_tm padded: 2*5 rows x 8    = 80
#define CAVW 1440      // A_vw: 4x4                    = 16
#define CWG0 1456      // 7*18*16 [k][c][o], s1-folded = 2016
#define CWG1 3472      // 7*16*16                      = 1792
#define CWG2 5264      // 1792
#define CBG  7056      // 3*7*16, s1-folded            = 336
#define CB1  7392      // 336
#define CWT  7728      // 3*7*16*16 [l][k][c][o], s2-folded = 5376
#define CCI  13104     // 3*16: sum_k(bt*s2+b2)        = 48
#define CTOT 13152     // 16B aligned

#define SACT CTOT                    // Y0: 9 planes, Y1: 8 planes
#define SMF  (SACT + 17*PL)          // 24712 floats
#define SMB  (SMF*4)                 // 98848 B -> 2 CTAs/SM

__device__ float gS[CTOT];

// ---- packed-f32x2 helpers (Blackwell) ----
__device__ __forceinline__ ULL f2fma(ULL a, ULL b, ULL c){
  ULL d; asm("fma.rn.f32x2 %0,%1,%2,%3;" : "=l"(d) : "l"(a), "l"(b), "l"(c)); return d;
}
__device__ __forceinline__ ULL f2add(ULL a, ULL b){
  ULL d; asm("add.rn.f32x2 %0,%1,%2;" : "=l"(d) : "l"(a), "l"(b)); return d;
}
__device__ __forceinline__ ULL pkdup(float a){
  ULL d; asm("mov.b64 %0,{%1,%1};" : "=l"(d) : "f"(a), "f"(a)); return d;
}
__device__ __forceinline__ ULL pk(float a, float b){
  ULL d; asm("mov.b64 %0,{%1,%2};" : "=l"(d) : "f"(a), "f"(b)); return d;
}
__device__ __forceinline__ float2 up2(ULL a){
  float2 v; asm("mov.b64 {%0,%1},%2;" : "=f"(v.x), "=f"(v.y) : "l"(a)); return v;
}
__device__ __forceinline__ ULL lds2(const float* p){ return *reinterpret_cast<const ULL*>(p); }
__device__ __forceinline__ void sts2(float* p, ULL v){ *reinterpret_cast<ULL*>(p) = v; }
__device__ __forceinline__ float4 lds4(const float* p){ return *reinterpret_cast<const float4*>(p); }

// ---------------- prep: fold BN scales into weights, pad A, transpose ----------------
__global__ void prep_kernel(const float* __restrict__ A_sp, const float* __restrict__ A_tm,
                            const float* __restrict__ A_vw,
                            const float* __restrict__ Wg0, const float* __restrict__ bg0,
                            const float* __restrict__ Wg,  const float* __restrict__ bg,
                            const float* __restrict__ bn1g, const float* __restrict__ bn1b,
                            const float* __restrict__ Wt,  const float* __restrict__ bt,
                            const float* __restrict__ bn2g, const float* __restrict__ bn2b)
{
  const int t = threadIdx.x;
  const float inv = rsqrtf(1.f + EPSF);
  for (int i = t; i < 1360; i += 256){
    int k = i / 340, r = i % 340, u = r / 20, vp = r % 20;
    gS[CASP + i] = (vp < 17) ? A_sp[(k*17 + u)*17 + vp] : 0.f;
  }
  for (int i = t; i < 80; i += 256){
    int k = i / 40, r = i % 40, tt = r / 8, tp = r % 8;
    gS[CATM + i] = (tp < 5) ? A_tm[(k*5 + tt)*5 + tp] : 0.f;
  }
  for (int i = t; i < 16; i += 256) gS[CAVW + i] = A_vw[i];
  for (int i = t; i < 2016; i += 256){
    int k = i / 288, r = i % 288, o = r / 18, c = r % 18;
    gS[CWG0 + (k*18 + c)*16 + o] = Wg0[i] * (bn1g[k*16 + o] * inv);
  }
  for (int i = t; i < 3584; i += 256){
    int l = i / 1792, r = i % 1792, k = r / 256, q = r % 256, o = q / 16, c = q % 16;
    gS[CWG1 + l*1792 + (k*16 + c)*16 + o] = Wg[i] * (bn1g[((l+1)*7 + k)*16 + o] * inv);
  }
  for (int i = t; i < 336; i += 256){
    float bgv = (i < 112) ? bg0[i] : bg[i - 112];
    gS[CBG + i] = bgv * (bn1g[i] * inv);
    gS[CB1 + i] = bn1b[i];
  }
  for (int i = t; i < 5376; i += 256){
    int l = i / 1792, r = i % 1792, k = r / 256, q = r % 256, o = q / 16, c = q % 16;
    gS[CWT + l*1792 + (k*16 + c)*16 + o] = Wt[i] * (bn2g[(l*7 + k)*16 + o] * inv);
  }
  for (int i = t; i < 48; i += 256){
    int l = i / 16, o = i % 16;
    float s = 0.f;
    for (int k = 0; k < 7; k++){
      int id = (l*7 + k)*16 + o;
      s += bt[id] * (bn2g[id] * inv) + bn2b[id];
    }
    gS[CCI + i] = s;
  }
}

// ---- phase A: conv1 (s1-folded) from register-stationary x -> y planes ----
template<int CIN>
__device__ __forceinline__ void phaseA(const float* __restrict__ sP, float* __restrict__ sY,
                                       int wb, int bb,
                                       const float (&xr0)[18], const float (&xr1)[18],
                                       int nd0, int nd1)
{
  ULL y0[8], y1[8];
  #pragma unroll
  for (int q = 0; q < 4; q++){
    UL2 b = *reinterpret_cast<const UL2*>(sP + bb + 4*q);
    y0[2*q] = b.x; y0[2*q+1] = b.y;
    y1[2*q] = b.x; y1[2*q+1] = b.y;
  }
  #pragma unroll
  for (int c = 0; c < CIN; c++){
    UL2 wA = *reinterpret_cast<const UL2*>(sP + wb + c*16);
    UL2 wB = *reinterpret_cast<const UL2*>(sP + wb + c*16 + 4);
    UL2 wC = *reinterpret_cast<const UL2*>(sP + wb + c*16 + 8);
    UL2 wD = *reinterpret_cast<const UL2*>(sP + wb + c*16 + 12);
    ULL xa = pkdup(xr0[c]), xb = pkdup(xr1[c]);
    y0[0] = f2fma(wA.x, xa, y0[0]); y1[0] = f2fma(wA.x, xb, y1[0]);
    y0[1] = f2fma(wA.y, xa, y0[1]); y1[1] = f2fma(wA.y, xb, y1[1]);
    y0[2] = f2fma(wB.x, xa, y0[2]); y1[2] = f2fma(wB.x, xb, y1[2]);
    y0[3] = f2fma(wB.y, xa, y0[3]); y1[3] = f2fma(wB.y, xb, y1[3]);
    y0[4] = f2fma(wC.x, xa, y0[4]); y1[4] = f2fma(wC.x, xb, y1[4]);
    y0[5] = f2fma(wC.y, xa, y0[5]); y1[5] = f2fma(wC.y, xb, y1[5]);
    y0[6] = f2fma(wD.x, xa, y0[6]); y1[6] = f2fma(wD.x, xb, y1[6]);
    y0[7] = f2fma(wD.y, xa, y0[7]); y1[7] = f2fma(wD.y, xb, y1[7]);
  }
  #pragma unroll
  for (int p = 0; p < 8; p++){
    sts2(sY + p*PL + nd0*2, y0[p]);
    sts2(sY + p*PL + nd1*2, y1[p]);
  }
}

// ---- phase C: conv2 (s2-folded) reading own aggregated rows (planes) ----
__device__ __forceinline__ void phaseC(const float* __restrict__ sP, const float* __restrict__ sY,
                                       int wb, int nd0, int nd1,
                                       ULL (&acc0)[8], ULL (&acc1)[8])
{
  float r0[16], r1[16];
  #pragma unroll
  for (int p = 0; p < 8; p++){
    float2 a = up2(lds2(sY + p*PL + nd0*2));
    r0[2*p] = a.x; r0[2*p+1] = a.y;
    float2 b = up2(lds2(sY + p*PL + nd1*2));
    r1[2*p] = b.x; r1[2*p+1] = b.y;
  }
  #pragma unroll
  for (int c = 0; c < 16; c++){
    UL2 wA = *reinterpret_cast<const UL2*>(sP + wb + c*16);
    UL2 wB = *reinterpret_cast<const UL2*>(sP + wb + c*16 + 4);
    UL2 wC = *reinterpret_cast<const UL2*>(sP + wb + c*16 + 8);
    UL2 wD = *reinterpret_cast<const UL2*>(sP + wb + c*16 + 12);
    ULL xa = pkdup(r0[c]), xb = pkdup(r1[c]);
    acc0[0] = f2fma(wA.x, xa, acc0[0]); acc1[0] = f2fma(wA.x, xb, acc1[0]);
    acc0[1] = f2fma(wA.y, xa, acc0[1]); acc1[1] = f2fma(wA.y, xb, acc1[1]);
    acc0[2] = f2fma(wB.x, xa, acc0[2]); acc1[2] = f2fma(wB.x, xb, acc1[2]);
    acc0[3] = f2fma(wB.y, xa, acc0[3]); acc1[3] = f2fma(wB.y, xb, acc1[3]);
    acc0[4] = f2fma(wC.x, xa, acc0[4]); acc1[4] = f2fma(wC.x, xb, acc1[4]);
    acc0[5] = f2fma(wC.y, xa, acc0[5]); acc1[5] = f2fma(wC.y, xb, acc1[5]);
    acc0[6] = f2fma(wD.x, xa, acc0[6]); acc1[6] = f2fma(wD.x, xb, acc1[6]);
    acc0[7] = f2fma(wD.y, xa, acc0[7]); acc1[7] = f2fma(wD.y, xb, acc1[7]);
  }
}

// ---- phase B slice bodies (in-place agg + b1 + ReLU on one channel-pair slice) ----
__device__ __forceinline__ void bsp_slice(const float* __restrict__ sP, float* __restrict__ sY,
                                          int L, int k, int cp, int g)
{
  float* base = sY + cp*PL + g*34;
  ULL ys[20];
  #pragma unroll
  for (int v = 0; v < 17; v++) ys[v] = lds2(base + v*2);
  ys[17] = 0ULL; ys[18] = 0ULL; ys[19] = 0ULL;
  const ULL b1 = lds2(sP + CB1 + (L*7 + k)*16 + 2*cp);
  const int ab = CASP + k*340;
  #pragma unroll
  for (int u = 0; u < 17; u++){
    ULL z = 0ULL;
    #pragma unroll
    for (int q = 0; q < 5; q++){
      float4 a = lds4(sP + ab + u*20 + 4*q);
      z = f2fma(ys[4*q + 0], pkdup(a.x), z);
      z = f2fma(ys[4*q + 1], pkdup(a.y), z);
      z = f2fma(ys[4*q + 2], pkdup(a.z), z);
      z = f2fma(ys[4*q + 3], pkdup(a.w), z);
    }
    float2 f = up2(f2add(z, b1));
    sts2(base + u*2, pk(fmaxf(f.x, 0.f), fmaxf(f.y, 0.f)));
  }
}

__device__ __forceinline__ void btm_slice(const float* __restrict__ sP, float* __restrict__ sY,
                                          int L, int k, int cp, int vw, int v)
{
  float* base = sY + cp*PL + (vw*85 + v)*2;
  ULL ys[5];
  #pragma unroll
  for (int tp = 0; tp < 5; tp++) ys[tp] = lds2(base + tp*34);
  const ULL b1 = lds2(sP + CB1 + (L*7 + k)*16 + 2*cp);
  const int ab = CATM + (k - 4)*40;
  #pragma unroll
  for (int t = 0; t < 5; t++){
    float4 a0 = lds4(sP + ab + t*8);
    float  a4 = sP[ab + t*8 + 4];
    ULL z = 0ULL;
    z = f2fma(ys[0], pkdup(a0.x), z);
    z = f2fma(ys[1], pkdup(a0.y), z);
    z = f2fma(ys[2], pkdup(a0.z), z);
    z = f2fma(ys[3], pkdup(a0.w), z);
    z = f2fma(ys[4], pkdup(a4),   z);
    float2 f = up2(f2add(z, b1));
    sts2(base + t*34, pk(fmaxf(f.x, 0.f), fmaxf(f.y, 0.f)));
  }
}

// ---- phase B pair drivers: both buffers in one window ----
__device__ __forceinline__ void bsp_pair(const float* __restrict__ sP,
                                         float* __restrict__ sY0, float* __restrict__ sY1,
                                         int tid, int L, int k0)
{
  #pragma unroll 1
  for (int it = tid; it < 320; it += 192){
    int b = (it >= 160); int s = it - b*160;
    int cp = s / 20, g = s - cp*20;
    bsp_slice(sP, b ? sY1 : sY0, L, k0 + b, cp, g);
  }
}

__device__ __forceinline__ void btm_pair(const float* __restrict__ sP,
                                         float* __restrict__ sY0, float* __restrict__ sY1,
                                         int tid, int L)
{
  #pragma unroll 1
  for (int it = tid; it < 1088; it += 192){
    int b = (it >= 544); int s = it - b*544;
    int cp = s / 68; int r = s - cp*68; int vw = r / 17; int v = r - vw*17;
    btm_slice(sP, b ? sY1 : sY0, L, 4 + b, cp, vw, v);
  }
}

__device__ __forceinline__ void bvw_all(const float* __restrict__ sP, float* __restrict__ sY,
                                        int tid, int L)
{
  const int b1b = CB1 + (L*7 + 6)*16;
  #pragma unroll 1
  for (int it = tid; it < 680; it += 192){
    int cp = it / 85; int r = it - cp*85; int t = r / 17; int v = r - t*17;
    float* base = sY + cp*PL + (t*17 + v)*2;
    ULL ys[4];
    #pragma unroll
    for (int vw = 0; vw < 4; vw++) ys[vw] = lds2(base + vw*170);
    const ULL b1 = lds2(sP + b1b + 2*cp);
    #pragma unroll
    for (int vo = 0; vo < 4; vo++){
      float4 a = lds4(sP + CAVW + vo*4);
      ULL z = 0ULL;
      z = f2fma(ys[0], pkdup(a.x), z);
      z = f2fma(ys[1], pkdup(a.y), z);
      z = f2fma(ys[2], pkdup(a.z), z);
      z = f2fma(ys[3], pkdup(a.w), z);
      float2 f = up2(f2add(z, b1));
      sts2(base + vo*170, pk(fmaxf(f.x, 0.f), fmaxf(f.y, 0.f)));
    }
  }
}

// ---- one layer, paired-branch windows; assumes A(0)->Y0, A(1)->Y1 already done+synced ----
template<int CIN>
__device__ __forceinline__ void run_layer(const float* __restrict__ sP,
    float* __restrict__ sY0, float* __restrict__ sY1,
    int tid, int L, int wgb, bool act, int nd0, int nd1,
    const float (&xr0)[18], const float (&xr1)[18],
    ULL (&acc0)[8], ULL (&acc1)[8])
{
  const int cinw = CIN*16;
  const int bL = L*7;
  // window 1: B(0,1) -> C(0,1) + A(2,3)
  bsp_pair(sP, sY0, sY1, tid, L, 0);
  __syncthreads();
  if (act){
    phaseC(sP, sY0, CWT + (bL+0)*256, nd0, nd1, acc0, acc1);
    phaseC(sP, sY1, CWT + (bL+1)*256, nd0, nd1, acc0, acc1);
    phaseA<CIN>(sP, sY0, wgb + 2*cinw, CBG + (bL+2)*16, xr0, xr1, nd0, nd1);
    phaseA<CIN>(sP, sY1, wgb + 3*cinw, CBG + (bL+3)*16, xr0, xr1, nd0, nd1);
  }
  __syncthreads();
  // window 2: B(2,3) -> C(2,3) + A(4,5)
  bsp_pair(sP, sY0, sY1, tid, L, 2);
  __syncthreads();
  if (act){
    phaseC(sP, sY0, CWT + (bL+2)*256, nd0, nd1, acc0, acc1);
    phaseC(sP, sY1, CWT + (bL+3)*256, nd0, nd1, acc0, acc1);
    phaseA<CIN>(sP, sY0, wgb + 4*cinw, CBG + (bL+4)*16, xr0, xr1, nd0, nd1);
    phaseA<CIN>(sP, sY1, wgb + 5*cinw, CBG + (bL+5)*16, xr0, xr1, nd0, nd1);
  }
  __syncthreads();
  // window 3: B(4,5) -> C(4,5) + A(6)
  btm_pair(sP, sY0, sY1, tid, L);
  __syncthreads();
  if (act){
    phaseC(sP, sY0, CWT + (bL+4)*256, nd0, nd1, acc0, acc1);
    phaseC(sP, sY1, CWT + (bL+5)*256, nd0, nd1, acc0, acc1);
    phaseA<CIN>(sP, sY0, wgb + 6*cinw, CBG + (bL+6)*16, xr0, xr1, nd0, nd1);
  }
  __syncthreads();
  // window 4: B(6) -> C(6)   (caller appends boundary / next-layer prologue + sync)
  bvw_all(sP, sY0, tid, L);
  __syncthreads();
  if (act) phaseC(sP, sY0, CWT + (bL+6)*256, nd0, nd1, acc0, acc1);
}

// ---------------- fused 3-layer ST-GCN: one CTA per (n, hw) ----------------
__global__ __launch_bounds__(192, 2)
void stgcn_kernel(const float* __restrict__ x, float* __restrict__ out)
{
  extern __shared__ __align__(16) float smf[];
  float* sP  = smf;
  float* sY0 = smf + SACT;          // 9 planes
  float* sY1 = sY0 + 9*PL;          // 8 planes

  const int hw  = blockIdx.x;
  const int n   = blockIdx.y;
  const int tid = threadIdx.x;

  for (int i = tid*4; i < CTOT; i += 192*4)
    *reinterpret_cast<float4*>(sP + i) = *reinterpret_cast<const float4*>(gS + i);
  // load x into Y0's 9 channel-pair planes
  {
    const float* xb = x + ((size_t)n * NODES * 18) * HW + hw;
    for (int i = tid; i < NODES*9; i += 192){
      int cp = i / NODES, node = i - cp*NODES;
      float v0 = xb[(size_t)(node*18 + 2*cp)     * HW];
      float v1 = xb[(size_t)(node*18 + 2*cp + 1) * HW];
      sts2(sY0 + cp*PL + node*2, pk(v0, v1));
    }
  }
  __syncthreads();

  const bool act = tid < 170;
  const int nd0 = tid, nd1 = tid + 170;

  ULL acc0[8], acc1[8];
  float xr0[18], xr1[18];

  if (act){
    #pragma unroll
    for (int cp = 0; cp < 9; cp++){
      float2 a = up2(lds2(sY0 + cp*PL + nd0*2));
      xr0[2*cp] = a.x; xr0[2*cp+1] = a.y;
      float2 b = up2(lds2(sY0 + cp*PL + nd1*2));
      xr1[2*cp] = b.x; xr1[2*cp+1] = b.y;
    }
    #pragma unroll
    for (int q = 0; q < 8; q++){
      ULL ci = lds2(sP + CCI + 2*q);
      acc0[q] = ci; acc1[q] = ci;
    }
    // prologue: A(0)->Y0 (own rows overwrite x, thread-local), A(1)->Y1
    phaseA<18>(sP, sY0, CWG0,       CBG,      xr0, xr1, nd0, nd1);
    phaseA<18>(sP, sY1, CWG0 + 288, CBG + 16, xr0, xr1, nd0, nd1);
  }
  __syncthreads();

  run_layer<18>(sP, sY0, sY1, tid, 0, CWG0, act, nd0, nd1, xr0, xr1, acc0, acc1);
  if (act){
    // boundary L0->L1: xr = relu(acc); acc = CI1 + 7*xr; prologue A(0,1) of L1
    #pragma unroll
    for (int q = 0; q < 8; q++){
      float ci0 = sP[CCI + 16 + 2*q], ci1 = sP[CCI + 16 + 2*q + 1];
      float2 a = up2(acc0[q]);
      float x0 = fmaxf(a.x, 0.f), x1 = fmaxf(a.y, 0.f);
      xr0[2*q] = x0; xr0[2*q+1] = x1;
      acc0[q] = pk(fmaf(7.f, x0, ci0), fmaf(7.f, x1, ci1));
      float2 b = up2(acc1[q]);
      float u0 = fmaxf(b.x, 0.f), u1 = fmaxf(b.y, 0.f);
      xr1[2*q] = u0; xr1[2*q+1] = u1;
      acc1[q] = pk(fmaf(7.f, u0, ci0), fmaf(7.f, u1, ci1));
    }
    phaseA<16>(sP, sY0, CWG1,       CBG + 112, xr0, xr1, nd0, nd1);
    phaseA<16>(sP, sY1, CWG1 + 256, CBG + 128, xr0, xr1, nd0, nd1);
  }
  __syncthreads();

  run_layer<16>(sP, sY0, sY1, tid, 1, CWG1, act, nd0, nd1, xr0, xr1, acc0, acc1);
  if (act){
    // boundary L1->L2
    #pragma unroll
    for (int q = 0; q < 8; q++){
      float ci0 = sP[CCI + 32 + 2*q], ci1 = sP[CCI + 32 + 2*q + 1];
      float2 a = up2(acc0[q]);
      float x0 = fmaxf(a.x, 0.f), x1 = fmaxf(a.y, 0.f);
      xr0[2*q] = x0; xr0[2*q+1] = x1;
      acc0[q] = pk(fmaf(7.f, x0, ci0), fmaf(7.f, x1, ci1));
      float2 b = up2(acc1[q]);
      float u0 = fmaxf(b.x, 0.f), u1 = fmaxf(b.y, 0.f);
      xr1[2*q] = u0; xr1[2*q+1] = u1;
      acc1[q] = pk(fmaf(7.f, u0, ci0), fmaf(7.f, u1, ci1));
    }
    phaseA<16>(sP, sY0, CWG2,       CBG + 224, xr0, xr1, nd0, nd1);
    phaseA<16>(sP, sY1, CWG2 + 256, CBG + 240, xr0, xr1, nd0, nd1);
  }
  __syncthreads();

  run_layer<16>(sP, sY0, sY1, tid, 2, CWG2, act, nd0, nd1, xr0, xr1, acc0, acc1);

  // ---- final ReLU + output ----
  if (act){
    float* o0 = out + ((size_t)(n*NODES + nd0) * 16) * HW + hw;
    float* o1 = out + ((size_t)(n*NODES + nd1) * 16) * HW + hw;
    #pragma unroll
    for (int q = 0; q < 8; q++){
      float2 a = up2(acc0[q]);
      o0[(size_t)(2*q)     * HW] = fmaxf(a.x, 0.f);
      o0[(size_t)(2*q + 1) * HW] = fmaxf(a.y, 0.f);
      float2 b = up2(acc1[q]);
      o1[(size_t)(2*q)     * HW] = fmaxf(b.x, 0.f);
      o1[(size_t)(2*q + 1) * HW] = fmaxf(b.y, 0.f);
    }
  }
}

extern "C" void kernel_launch(void* const* d_in, const int* in_sizes, int n_in,
                              void* d_out, int out_size)
{
  (void)in_sizes; (void)n_in; (void)out_size;
  const float* x    = (const float*)d_in[0];
  const float* A_sp = (const float*)d_in[1];
  const float* A_tm = (const float*)d_in[2];
  const float* A_vw = (const float*)d_in[3];
  const float* Wg0  = (const float*)d_in[4];
  const float* bg0  = (const float*)d_in[5];
  const float* Wg   = (const float*)d_in[6];
  const float* bg   = (const float*)d_in[7];
  const float* bn1g = (const float*)d_in[8];
  const float* bn1b = (const float*)d_in[9];
  const float* Wt   = (const float*)d_in[10];
  const float* bt   = (const float*)d_in[11];
  const float* bn2g = (const float*)d_in[12];
  const float* bn2b = (const float*)d_in[13];

  cudaFuncSetAttribute(stgcn_kernel, cudaFuncAttributeMaxDynamicSharedMemorySize, SMB);

  prep_kernel<<<1, 256>>>(A_sp, A_tm, A_vw, Wg0, bg0, Wg, bg,
                          bn1g, bn1b, Wt, bt, bn2g, bn2b);
  stgcn_kernel<<<dim3(HW, NB), 192, SMB>>>(x, (float*)d_out);
}